// round 2
// baseline (speedup 1.0000x reference)
#include <cuda_runtime.h>
#include <cuda_bf16.h>
#include <math_constants.h>

// Problem constants (fixed by the reference setup)
#define NBATCH   512
#define NPOINTS  32768
#define THREADS  128
#define PTS_PER_THREAD 4
#define POINTS_PER_BLOCK (THREADS * PTS_PER_THREAD)   // 512
#define POINT_BLOCKS (NPOINTS / POINTS_PER_BLOCK)     // 64
#define BATCH_TILES  8
#define BATCH_PER_TILE (NBATCH / BATCH_TILES)         // 64

// Per-batch delta-affine table: 9 floats dR (row-major) + 3 floats dt
__device__ float g_mats[NBATCH * 12];

__device__ __forceinline__ float fsqrt_approx(float x) {
    float r;
    asm("sqrt.approx.f32 %0, %1;" : "=f"(r) : "f"(x));
    return r;
}

// R = Rz @ Ry @ Rx  (matching the reference einsum)
__device__ __forceinline__ void euler2rot(float tx, float ty, float tz, float R[9]) {
    float cx = __cosf(tx), sx = __sinf(tx);
    float cy = __cosf(ty), sy = __sinf(ty);
    float cz = __cosf(tz), sz = __sinf(tz);
    R[0] =  cz * cy;
    R[1] =  cz * sy * sx + sz * cx;
    R[2] = -cz * sy * cx + sz * sx;
    R[3] = -sz * cy;
    R[4] = -sz * sy * sx + cz * cx;
    R[5] =  sz * sy * cx + cz * sx;
    R[6] =  sy;
    R[7] = -cy * sx;
    R[8] =  cy * cx;
}

// Kernel A: build per-batch (dR, dt) table; zero output scalar.
__global__ void build_mats_kernel(const float* __restrict__ output,
                                  const float* __restrict__ target,
                                  const float* __restrict__ rot_cen,
                                  float* __restrict__ out) {
    int b = blockIdx.x * blockDim.x + threadIdx.x;
    if (b == 0) out[0] = 0.0f;
    if (b >= NBATCH) return;

    const float D2R = 0.017453292519943295f;  // pi/180

    const float* pt = target + b * 6;
    const float* po = output + b * 6;

    float R1[9], R2[9];
    euler2rot(pt[0] * D2R, pt[1] * D2R, pt[2] * D2R, R1);
    euler2rot(po[0] * D2R, po[1] * D2R, po[2] * D2R, R2);

    float dR[9];
#pragma unroll
    for (int i = 0; i < 9; i++) dR[i] = R1[i] - R2[i];

    float c0 = rot_cen[0], c1 = rot_cen[1], c2 = rot_cen[2];
    // dt = (t1 - t2) - dR @ rot_cen
    float dt0 = (pt[3] - po[3]) - (dR[0] * c0 + dR[1] * c1 + dR[2] * c2);
    float dt1 = (pt[4] - po[4]) - (dR[3] * c0 + dR[4] * c1 + dR[5] * c2);
    float dt2 = (pt[5] - po[5]) - (dR[6] * c0 + dR[7] * c1 + dR[8] * c2);

    float* m = &g_mats[b * 12];
#pragma unroll
    for (int i = 0; i < 9; i++) m[i] = dR[i];
    m[9]  = dt0;
    m[10] = dt1;
    m[11] = dt2;
}

// Kernel B: accumulate sum_{b,n} w_n * || dR_b p_n + dt_b ||
__global__ __launch_bounds__(THREADS)
void vm_loss_kernel(const float4* __restrict__ cube, float* __restrict__ out) {
    __shared__ float sm[BATCH_PER_TILE * 12];

    int tid = threadIdx.x;
    int bbase = blockIdx.y * BATCH_PER_TILE;

    // Load this tile's 64 matrices into smem (vectorized through float4)
    const float4* gsrc = reinterpret_cast<const float4*>(&g_mats[bbase * 12]);
    float4* sdst = reinterpret_cast<float4*>(sm);
#pragma unroll
    for (int i = tid; i < BATCH_PER_TILE * 3; i += THREADS)
        sdst[i] = gsrc[i];
    __syncthreads();

    int pbase = blockIdx.x * POINTS_PER_BLOCK + tid;
    float4 p0 = cube[pbase];
    float4 p1 = cube[pbase + THREADS];
    float4 p2 = cube[pbase + 2 * THREADS];
    float4 p3 = cube[pbase + 3 * THREADS];

    float acc = 0.0f;

#pragma unroll 2
    for (int b = 0; b < BATCH_PER_TILE; b++) {
        const float4* mv = reinterpret_cast<const float4*>(&sm[b * 12]);
        float4 r0 = mv[0];   // m00 m01 m02 m10
        float4 r1 = mv[1];   // m11 m12 m20 m21
        float4 r2 = mv[2];   // m22 t0  t1  t2

        float m00 = r0.x, m01 = r0.y, m02 = r0.z, m10 = r0.w;
        float m11 = r1.x, m12 = r1.y, m20 = r1.z, m21 = r1.w;
        float m22 = r2.x, t0 = r2.y, t1 = r2.z, t2 = r2.w;

#define POINT_DIST(P)                                                          \
        {                                                                      \
            float y0 = fmaf(m00, P.x, fmaf(m01, P.y, fmaf(m02, P.z, t0)));     \
            float y1 = fmaf(m10, P.x, fmaf(m11, P.y, fmaf(m12, P.z, t1)));     \
            float y2 = fmaf(m20, P.x, fmaf(m21, P.y, fmaf(m22, P.z, t2)));     \
            float s  = fmaf(y0, y0, fmaf(y1, y1, y2 * y2));                    \
            acc = fmaf(P.w, fsqrt_approx(s), acc);                             \
        }

        POINT_DIST(p0)
        POINT_DIST(p1)
        POINT_DIST(p2)
        POINT_DIST(p3)
#undef POINT_DIST
    }

    // Block reduction
#pragma unroll
    for (int o = 16; o > 0; o >>= 1)
        acc += __shfl_down_sync(0xffffffffu, acc, o);

    __shared__ float warpsum[THREADS / 32];
    int lane = tid & 31, wid = tid >> 5;
    if (lane == 0) warpsum[wid] = acc;
    __syncthreads();

    if (tid == 0) {
        float s = 0.0f;
#pragma unroll
        for (int w = 0; w < THREADS / 32; w++) s += warpsum[w];
        const float SCALE = 1.0f / ((float)NBATCH * (float)NPOINTS);
        atomicAdd(out, s * SCALE);
    }
}

extern "C" void kernel_launch(void* const* d_in, const int* in_sizes, int n_in,
                              void* d_out, int out_size) {
    const float* output  = (const float*)d_in[0];
    const float* target  = (const float*)d_in[1];
    const float* cube    = (const float*)d_in[2];
    const float* rot_cen = (const float*)d_in[3];
    float* out = (float*)d_out;

    build_mats_kernel<<<2, 256>>>(output, target, rot_cen, out);

    dim3 grid(POINT_BLOCKS, BATCH_TILES);
    vm_loss_kernel<<<grid, THREADS>>>(
        reinterpret_cast<const float4*>(cube), out);
}

// round 4
// speedup vs baseline: 1.0828x; 1.0828x over previous
#include <cuda_runtime.h>
#include <cuda_bf16.h>

// Problem constants (fixed by the reference setup)
#define NBATCH   512
#define NPOINTS  32768
#define THREADS  128
#define PTS_PER_THREAD 4
#define POINTS_PER_BLOCK (THREADS * PTS_PER_THREAD)   // 512
#define POINT_BLOCKS (NPOINTS / POINTS_PER_BLOCK)     // 64
#define BATCH_TILES  16
#define BATCH_PER_TILE (NBATCH / BATCH_TILES)         // 32
#define NPARTIAL (POINT_BLOCKS * BATCH_TILES)         // 1024

__device__ float g_partial[NPARTIAL];

typedef unsigned long long u64;

// ---- packed f32x2 helpers (Blackwell) ----
__device__ __forceinline__ u64 pk2(float lo, float hi) {
    u64 r;
    asm("mov.b64 %0, {%1, %2};" : "=l"(r) : "f"(lo), "f"(hi));
    return r;
}
__device__ __forceinline__ void upk2(u64 v, float& lo, float& hi) {
    asm("mov.b64 {%0, %1}, %2;" : "=f"(lo), "=f"(hi) : "l"(v));
}
__device__ __forceinline__ u64 fma2(u64 a, u64 b, u64 c) {
    u64 d;
    asm("fma.rn.f32x2 %0, %1, %2, %3;" : "=l"(d) : "l"(a), "l"(b), "l"(c));
    return d;
}
__device__ __forceinline__ u64 mul2(u64 a, u64 b) {
    u64 d;
    asm("mul.rn.f32x2 %0, %1, %2;" : "=l"(d) : "l"(a), "l"(b));
    return d;
}
__device__ __forceinline__ float fsqrt_approx(float x) {
    float r;
    asm("sqrt.approx.f32 %0, %1;" : "=f"(r) : "f"(x));
    return r;
}

// R = Rz @ Ry @ Rx  (matching the reference einsum)
__device__ __forceinline__ void euler2rot(float tx, float ty, float tz, float R[9]) {
    float cx = __cosf(tx), sx = __sinf(tx);
    float cy = __cosf(ty), sy = __sinf(ty);
    float cz = __cosf(tz), sz = __sinf(tz);
    R[0] =  cz * cy;
    R[1] =  cz * sy * sx + sz * cx;
    R[2] = -cz * sy * cx + sz * sx;
    R[3] = -sz * cy;
    R[4] = -sz * sy * sx + cz * cx;
    R[5] =  sz * sy * cx + cz * sx;
    R[6] =  sy;
    R[7] = -cy * sx;
    R[8] =  cy * cx;
}

// Main kernel: builds this tile's delta-affine matrices in-block (threads 0-31),
// then accumulates sum_{b,n} w_n * || dR_b p_n + dt_b || over its point slab.
// Matrices stored in smem LANE-DUPLICATED so packed f32x2 FMA needs no MOVs:
//   per batch (24 floats): m00 m00 m01 m01 m02 m02 t0 t0 | m10.. t1 t1 | m20.. t2 t2
__global__ __launch_bounds__(THREADS)
void vm_loss_kernel(const float4* __restrict__ cube,
                    const float* __restrict__ output,
                    const float* __restrict__ target,
                    const float* __restrict__ rot_cen) {
    __shared__ ulonglong2 smat[BATCH_PER_TILE * 6];   // 3 KB

    int tid = threadIdx.x;
    int bbase = blockIdx.y * BATCH_PER_TILE;

    // ---- load this thread's 4 points (independent of the matrix build) ----
    int pbase = blockIdx.x * POINTS_PER_BLOCK + tid;
    float4 p0 = cube[pbase];
    float4 p1 = cube[pbase + THREADS];
    float4 p2 = cube[pbase + 2 * THREADS];
    float4 p3 = cube[pbase + 3 * THREADS];

    // ---- threads 0..31 build the 32 matrices for this batch tile ----
    if (tid < BATCH_PER_TILE) {
        int b = bbase + tid;
        const float D2R = 0.017453292519943295f;  // pi/180
        const float* pt = target + b * 6;
        const float* po = output + b * 6;

        float R1[9], R2[9];
        euler2rot(pt[0] * D2R, pt[1] * D2R, pt[2] * D2R, R1);
        euler2rot(po[0] * D2R, po[1] * D2R, po[2] * D2R, R2);

        float dR[9];
#pragma unroll
        for (int i = 0; i < 9; i++) dR[i] = R1[i] - R2[i];

        float c0 = rot_cen[0], c1 = rot_cen[1], c2 = rot_cen[2];
        float dt0 = (pt[3] - po[3]) - (dR[0] * c0 + dR[1] * c1 + dR[2] * c2);
        float dt1 = (pt[4] - po[4]) - (dR[3] * c0 + dR[4] * c1 + dR[5] * c2);
        float dt2 = (pt[5] - po[5]) - (dR[6] * c0 + dR[7] * c1 + dR[8] * c2);

        float* smf = reinterpret_cast<float*>(smat) + tid * 24;
#pragma unroll
        for (int r = 0; r < 3; r++) {
            smf[r * 8 + 0] = dR[r * 3 + 0];  smf[r * 8 + 1] = dR[r * 3 + 0];
            smf[r * 8 + 2] = dR[r * 3 + 1];  smf[r * 8 + 3] = dR[r * 3 + 1];
            smf[r * 8 + 4] = dR[r * 3 + 2];  smf[r * 8 + 5] = dR[r * 3 + 2];
        }
        smf[6]  = dt0; smf[7]  = dt0;
        smf[14] = dt1; smf[15] = dt1;
        smf[22] = dt2; smf[23] = dt2;
    }

    // ---- pack points into f32x2 pairs ----
    u64 px01 = pk2(p0.x, p1.x), py01 = pk2(p0.y, p1.y);
    u64 pz01 = pk2(p0.z, p1.z), w01  = pk2(p0.w, p1.w);
    u64 px23 = pk2(p2.x, p3.x), py23 = pk2(p2.y, p3.y);
    u64 pz23 = pk2(p2.z, p3.z), w23  = pk2(p2.w, p3.w);

    __syncthreads();

    u64 acc01 = 0ull, acc23 = 0ull;   // packed {0.0f, 0.0f}

#pragma unroll 2
    for (int b = 0; b < BATCH_PER_TILE; b++) {
        const ulonglong2* mv = &smat[b * 6];
        ulonglong2 q0 = mv[0];   // {m00,m00} {m01,m01}
        ulonglong2 q1 = mv[1];   // {m02,m02} {t0,t0}
        ulonglong2 q2 = mv[2];   // {m10,m10} {m11,m11}
        ulonglong2 q3 = mv[3];   // {m12,m12} {t1,t1}
        ulonglong2 q4 = mv[4];   // {m20,m20} {m21,m21}
        ulonglong2 q5 = mv[5];   // {m22,m22} {t2,t2}

#define PAIR_DIST(PX, PY, PZ, W, ACC)                                          \
        {                                                                      \
            u64 y0 = fma2(q0.x, PX, fma2(q0.y, PY, fma2(q1.x, PZ, q1.y)));     \
            u64 y1 = fma2(q2.x, PX, fma2(q2.y, PY, fma2(q3.x, PZ, q3.y)));     \
            u64 y2 = fma2(q4.x, PX, fma2(q4.y, PY, fma2(q5.x, PZ, q5.y)));     \
            u64 s2 = fma2(y0, y0, fma2(y1, y1, mul2(y2, y2)));                 \
            float slo, shi;                                                    \
            upk2(s2, slo, shi);                                                \
            u64 r2 = pk2(fsqrt_approx(slo), fsqrt_approx(shi));                \
            ACC = fma2(W, r2, ACC);                                            \
        }

        PAIR_DIST(px01, py01, pz01, w01, acc01)
        PAIR_DIST(px23, py23, pz23, w23, acc23)
#undef PAIR_DIST
    }

    float a0, a1, a2, a3;
    upk2(acc01, a0, a1);
    upk2(acc23, a2, a3);
    float acc = (a0 + a1) + (a2 + a3);

    // ---- block reduction ----
#pragma unroll
    for (int o = 16; o > 0; o >>= 1)
        acc += __shfl_down_sync(0xffffffffu, acc, o);

    __shared__ float warpsum[THREADS / 32];
    int lane = tid & 31, wid = tid >> 5;
    if (lane == 0) warpsum[wid] = acc;
    __syncthreads();

    if (tid == 0) {
        float s = 0.0f;
#pragma unroll
        for (int w = 0; w < THREADS / 32; w++) s += warpsum[w];
        g_partial[blockIdx.y * POINT_BLOCKS + blockIdx.x] = s;
    }
}

// Finalize: reduce the 1024 block partials into the scalar output.
__global__ __launch_bounds__(1024)
void finalize_kernel(float* __restrict__ out) {
    int tid = threadIdx.x;
    float v = g_partial[tid];

#pragma unroll
    for (int o = 16; o > 0; o >>= 1)
        v += __shfl_down_sync(0xffffffffu, v, o);

    __shared__ float wsum[32];
    int lane = tid & 31, wid = tid >> 5;
    if (lane == 0) wsum[wid] = v;
    __syncthreads();

    if (wid == 0) {
        float s = wsum[lane];
#pragma unroll
        for (int o = 16; o > 0; o >>= 1)
            s += __shfl_down_sync(0xffffffffu, s, o);
        if (lane == 0) {
            const float SCALE = 1.0f / ((float)NBATCH * (float)NPOINTS);
            out[0] = s * SCALE;
        }
    }
}

extern "C" void kernel_launch(void* const* d_in, const int* in_sizes, int n_in,
                              void* d_out, int out_size) {
    const float* output  = (const float*)d_in[0];
    const float* target  = (const float*)d_in[1];
    const float* cube    = (const float*)d_in[2];
    const float* rot_cen = (const float*)d_in[3];
    float* out = (float*)d_out;

    dim3 grid(POINT_BLOCKS, BATCH_TILES);
    vm_loss_kernel<<<grid, THREADS>>>(
        reinterpret_cast<const float4*>(cube), output, target, rot_cen);

    finalize_kernel<<<1, NPARTIAL>>>(out);
}

// round 5
// speedup vs baseline: 1.0976x; 1.0137x over previous
#include <cuda_runtime.h>
#include <cuda_bf16.h>

// Problem constants (fixed by the reference setup)
#define NBATCH   512
#define NPOINTS  32768
#define THREADS  128
#define PTS_PER_THREAD 4
#define POINTS_PER_BLOCK (THREADS * PTS_PER_THREAD)   // 512
#define POINT_BLOCKS (NPOINTS / POINTS_PER_BLOCK)     // 64
#define BATCH_TILES  16
#define BATCH_PER_TILE (NBATCH / BATCH_TILES)         // 32
#define NBLOCKS (POINT_BLOCKS * BATCH_TILES)          // 1024

__device__ float g_partial[NBLOCKS];
__device__ unsigned int g_sem = 0;

typedef unsigned long long u64;

// ---- packed f32x2 helpers (Blackwell) ----
__device__ __forceinline__ u64 pk2(float lo, float hi) {
    u64 r;
    asm("mov.b64 %0, {%1, %2};" : "=l"(r) : "f"(lo), "f"(hi));
    return r;
}
__device__ __forceinline__ void upk2(u64 v, float& lo, float& hi) {
    asm("mov.b64 {%0, %1}, %2;" : "=f"(lo), "=f"(hi) : "l"(v));
}
__device__ __forceinline__ u64 fma2(u64 a, u64 b, u64 c) {
    u64 d;
    asm("fma.rn.f32x2 %0, %1, %2, %3;" : "=l"(d) : "l"(a), "l"(b), "l"(c));
    return d;
}
__device__ __forceinline__ u64 mul2(u64 a, u64 b) {
    u64 d;
    asm("mul.rn.f32x2 %0, %1, %2;" : "=l"(d) : "l"(a), "l"(b));
    return d;
}
__device__ __forceinline__ float fsqrt_approx(float x) {
    float r;
    asm("sqrt.approx.f32 %0, %1;" : "=f"(r) : "f"(x));
    return r;
}

// R = Rz @ Ry @ Rx  (matching the reference einsum)
__device__ __forceinline__ void euler2rot(float tx, float ty, float tz, float R[9]) {
    float cx = __cosf(tx), sx = __sinf(tx);
    float cy = __cosf(ty), sy = __sinf(ty);
    float cz = __cosf(tz), sz = __sinf(tz);
    R[0] =  cz * cy;
    R[1] =  cz * sy * sx + sz * cx;
    R[2] = -cz * sy * cx + sz * sx;
    R[3] = -sz * cy;
    R[4] = -sz * sy * sx + cz * cx;
    R[5] =  sz * sy * cx + cz * sx;
    R[6] =  sy;
    R[7] = -cy * sx;
    R[8] =  cy * cx;
}

// Single fused kernel:
//  1. threads 0..31 build this tile's 32 delta-affine matrices (lane-duplicated
//     in smem so packed f32x2 FMA needs no per-iteration MOVs)
//  2. main loop: acc += w_n * || dR_b p_n + dt_b || over the block's slab
//  3. block partial -> g_partial; the LAST block (device counter) reduces all
//     partials, writes d_out, and resets the counter for graph replay.
__global__ __launch_bounds__(THREADS)
void vm_loss_kernel(const float4* __restrict__ cube,
                    const float* __restrict__ output,
                    const float* __restrict__ target,
                    const float* __restrict__ rot_cen,
                    float* __restrict__ out) {
    __shared__ ulonglong2 smat[BATCH_PER_TILE * 6];   // 3 KB
    __shared__ float warpsum[THREADS / 32];
    __shared__ unsigned int s_isLast;

    int tid = threadIdx.x;
    int bbase = blockIdx.y * BATCH_PER_TILE;

    // ---- load this thread's 4 points (independent of the matrix build) ----
    int pbase = blockIdx.x * POINTS_PER_BLOCK + tid;
    float4 p0 = cube[pbase];
    float4 p1 = cube[pbase + THREADS];
    float4 p2 = cube[pbase + 2 * THREADS];
    float4 p3 = cube[pbase + 3 * THREADS];

    // ---- threads 0..31 build the 32 matrices for this batch tile ----
    if (tid < BATCH_PER_TILE) {
        int b = bbase + tid;
        const float D2R = 0.017453292519943295f;  // pi/180
        const float* pt = target + b * 6;
        const float* po = output + b * 6;

        float R1[9], R2[9];
        euler2rot(pt[0] * D2R, pt[1] * D2R, pt[2] * D2R, R1);
        euler2rot(po[0] * D2R, po[1] * D2R, po[2] * D2R, R2);

        float dR[9];
#pragma unroll
        for (int i = 0; i < 9; i++) dR[i] = R1[i] - R2[i];

        float c0 = rot_cen[0], c1 = rot_cen[1], c2 = rot_cen[2];
        float dt0 = (pt[3] - po[3]) - (dR[0] * c0 + dR[1] * c1 + dR[2] * c2);
        float dt1 = (pt[4] - po[4]) - (dR[3] * c0 + dR[4] * c1 + dR[5] * c2);
        float dt2 = (pt[5] - po[5]) - (dR[6] * c0 + dR[7] * c1 + dR[8] * c2);

        float* smf = reinterpret_cast<float*>(smat) + tid * 24;
#pragma unroll
        for (int r = 0; r < 3; r++) {
            smf[r * 8 + 0] = dR[r * 3 + 0];  smf[r * 8 + 1] = dR[r * 3 + 0];
            smf[r * 8 + 2] = dR[r * 3 + 1];  smf[r * 8 + 3] = dR[r * 3 + 1];
            smf[r * 8 + 4] = dR[r * 3 + 2];  smf[r * 8 + 5] = dR[r * 3 + 2];
        }
        smf[6]  = dt0; smf[7]  = dt0;
        smf[14] = dt1; smf[15] = dt1;
        smf[22] = dt2; smf[23] = dt2;
    }

    // ---- pack points into f32x2 pairs ----
    u64 px01 = pk2(p0.x, p1.x), py01 = pk2(p0.y, p1.y);
    u64 pz01 = pk2(p0.z, p1.z), w01  = pk2(p0.w, p1.w);
    u64 px23 = pk2(p2.x, p3.x), py23 = pk2(p2.y, p3.y);
    u64 pz23 = pk2(p2.z, p3.z), w23  = pk2(p2.w, p3.w);

    __syncthreads();

    u64 acc01 = 0ull, acc23 = 0ull;   // packed {0.0f, 0.0f}

#pragma unroll 2
    for (int b = 0; b < BATCH_PER_TILE; b++) {
        const ulonglong2* mv = &smat[b * 6];
        ulonglong2 q0 = mv[0];   // {m00,m00} {m01,m01}
        ulonglong2 q1 = mv[1];   // {m02,m02} {t0,t0}
        ulonglong2 q2 = mv[2];   // {m10,m10} {m11,m11}
        ulonglong2 q3 = mv[3];   // {m12,m12} {t1,t1}
        ulonglong2 q4 = mv[4];   // {m20,m20} {m21,m21}
        ulonglong2 q5 = mv[5];   // {m22,m22} {t2,t2}

#define PAIR_DIST(PX, PY, PZ, W, ACC)                                          \
        {                                                                      \
            u64 y0 = fma2(q0.x, PX, fma2(q0.y, PY, fma2(q1.x, PZ, q1.y)));     \
            u64 y1 = fma2(q2.x, PX, fma2(q2.y, PY, fma2(q3.x, PZ, q3.y)));     \
            u64 y2 = fma2(q4.x, PX, fma2(q4.y, PY, fma2(q5.x, PZ, q5.y)));     \
            u64 s2 = fma2(y0, y0, fma2(y1, y1, mul2(y2, y2)));                 \
            float slo, shi;                                                    \
            upk2(s2, slo, shi);                                                \
            u64 r2 = pk2(fsqrt_approx(slo), fsqrt_approx(shi));                \
            ACC = fma2(W, r2, ACC);                                            \
        }

        PAIR_DIST(px01, py01, pz01, w01, acc01)
        PAIR_DIST(px23, py23, pz23, w23, acc23)
#undef PAIR_DIST
    }

    float a0, a1, a2, a3;
    upk2(acc01, a0, a1);
    upk2(acc23, a2, a3);
    float acc = (a0 + a1) + (a2 + a3);

    // ---- block reduction ----
#pragma unroll
    for (int o = 16; o > 0; o >>= 1)
        acc += __shfl_down_sync(0xffffffffu, acc, o);

    int lane = tid & 31, wid = tid >> 5;
    if (lane == 0) warpsum[wid] = acc;
    __syncthreads();

    if (tid == 0) {
        float s = 0.0f;
#pragma unroll
        for (int w = 0; w < THREADS / 32; w++) s += warpsum[w];
        int bid = blockIdx.y * POINT_BLOCKS + blockIdx.x;
        g_partial[bid] = s;
        __threadfence();
        unsigned int prev = atomicAdd(&g_sem, 1u);
        s_isLast = (prev == NBLOCKS - 1) ? 1u : 0u;
    }
    __syncthreads();

    // ---- last block reduces all partials and writes the output ----
    if (s_isLast) {
        float v = 0.0f;
#pragma unroll
        for (int i = 0; i < NBLOCKS / THREADS; i++)
            v += g_partial[tid + i * THREADS];

#pragma unroll
        for (int o = 16; o > 0; o >>= 1)
            v += __shfl_down_sync(0xffffffffu, v, o);

        if (lane == 0) warpsum[wid] = v;
        __syncthreads();

        if (tid == 0) {
            float s = 0.0f;
#pragma unroll
            for (int w = 0; w < THREADS / 32; w++) s += warpsum[w];
            const float SCALE = 1.0f / ((float)NBATCH * (float)NPOINTS);
            out[0] = s * SCALE;
            g_sem = 0;          // reset for next graph replay
        }
    }
}

extern "C" void kernel_launch(void* const* d_in, const int* in_sizes, int n_in,
                              void* d_out, int out_size) {
    const float* output  = (const float*)d_in[0];
    const float* target  = (const float*)d_in[1];
    const float* cube    = (const float*)d_in[2];
    const float* rot_cen = (const float*)d_in[3];
    float* out = (float*)d_out;

    dim3 grid(POINT_BLOCKS, BATCH_TILES);
    vm_loss_kernel<<<grid, THREADS>>>(
        reinterpret_cast<const float4*>(cube), output, target, rot_cen, out);
}